// round 4
// baseline (speedup 1.0000x reference)
#include <cuda_runtime.h>

#define CCH 256
#define HH 64
#define WW 64
#define NPIX (HH * WW)

// 4 * 4096 * 256 floats = 16 MB channels-last scratch
__device__ float g_feat_nhwc[4 * NPIX * CCH];

// NCHW -> NHWC transpose: per batch, [C=256][P=4096] -> [P][C]
__global__ __launch_bounds__(256) void transpose_kernel(const float* __restrict__ feat)
{
    __shared__ float tile[32][33];
    const int b  = blockIdx.z;
    const int p0 = blockIdx.x * 32;
    const int c0 = blockIdx.y * 32;
    const int tx = threadIdx.x;
    const int ty = threadIdx.y;
    const float* src = feat + (size_t)b * CCH * NPIX;
    float* dst = g_feat_nhwc + (size_t)b * NPIX * CCH;
#pragma unroll
    for (int i = 0; i < 32; i += 8)
        tile[ty + i][tx] = src[(size_t)(c0 + ty + i) * NPIX + (p0 + tx)];
    __syncthreads();
#pragma unroll
    for (int i = 0; i < 32; i += 8)
        dst[(size_t)(p0 + ty + i) * CCH + (c0 + tx)] = tile[tx][ty + i];
}

// Block = 32 threads (ONE warp). Each block: one ROI, 128 channels
// (lane = 4 consecutive channels via float4 / LDG.128).
// Maxpool fused in registers (running row-max); staging smem in natural
// output order with rotated component stores (bank-conflict-free).
__global__ __launch_bounds__(32) void roialign_maxpool_kernel(
    const float* __restrict__ rois,
    float* __restrict__ out)
{
    __shared__ float s_pool[128 * 49];   // [ch][49] == output order
    __shared__ int4   s_off[64];
    __shared__ float4 s_w[64];
    __shared__ int    s_b;

    const int roi  = blockIdx.x >> 1;
    const int half = blockIdx.x & 1;
    const int lane = threadIdx.x;

    // ---- per-ROI geometry: 64 bins, 2 per lane (valid folded into weights) ----
    {
        const float* r = rois + (size_t)roi * 5;
        const float x1 = r[1] * 0.0625f;
        const float y1 = r[2] * 0.0625f;
        const float x2 = r[3] * 0.0625f;
        const float y2 = r[4] * 0.0625f;
        const float bh = (y2 - y1) / 7.0f;
        const float bw = (x2 - x1) / 7.0f;
#pragma unroll
        for (int t = 0; t < 2; t++) {
            const int bin = lane + t * 32;
            const int j = bin >> 3;
            const int i = bin & 7;
            const float ys = y1 + bh * (float)j;
            const float xs = x1 + bw * (float)i;
            const bool valid = (ys >= 0.0f) && (ys < (float)HH) &&
                               (xs >= 0.0f) && (xs < (float)WW);
            const float y0 = floorf(ys);
            const float x0 = floorf(xs);
            const float ly = ys - y0;
            const float lx = xs - x0;
            int iy0 = min(max((int)y0, 0), HH - 1);
            int ix0 = min(max((int)x0, 0), WW - 1);
            int iy1 = min(iy0 + 1, HH - 1);
            int ix1 = min(ix0 + 1, WW - 1);
            float hy = 1.0f - ly, hx = 1.0f - lx;
            float w00 = hy * hx, w01 = hy * lx, w10 = ly * hx, w11 = ly * lx;
            if (!valid) { w00 = 0.0f; w01 = 0.0f; w10 = 0.0f; w11 = 0.0f; }
            // offsets in float4 units: pixel * (256/4)
            s_off[bin] = make_int4((iy0 * WW + ix0) * 64, (iy0 * WW + ix1) * 64,
                                   (iy1 * WW + ix0) * 64, (iy1 * WW + ix1) * 64);
            s_w[bin] = make_float4(w00, w01, w10, w11);
        }
        if (lane == 0) s_b = (int)r[0];
    }
    __syncthreads();

    const float4* p = (const float4*)g_feat_nhwc
                    + (size_t)s_b * (NPIX * CCH / 4)
                    + half * 32 + lane;          // channel base = half*128 + 4*lane
    const int rot = (lane >> 3) & 3;
    const int chb = 4 * lane;

    float4 rowmax[7];

    for (int j = 0; j < 8; j++) {
        float4 vprev;
#pragma unroll
        for (int i = 0; i < 8; i++) {
            const int bin = j * 8 + i;
            const int4   o = s_off[bin];
            const float4 w = s_w[bin];
            const float4 t0 = __ldg(p + o.x);
            const float4 t1 = __ldg(p + o.y);
            const float4 t2 = __ldg(p + o.z);
            const float4 t3 = __ldg(p + o.w);
            float4 v;
            v.x = w.x * t0.x + w.y * t1.x + w.z * t2.x + w.w * t3.x;
            v.y = w.x * t0.y + w.y * t1.y + w.z * t2.y + w.w * t3.y;
            v.z = w.x * t0.z + w.y * t1.z + w.z * t2.z + w.w * t3.z;
            v.w = w.x * t0.w + w.y * t1.w + w.z * t2.w + w.w * t3.w;
            if (i > 0) {
                float4 rm;
                rm.x = fmaxf(vprev.x, v.x);
                rm.y = fmaxf(vprev.y, v.y);
                rm.z = fmaxf(vprev.z, v.z);
                rm.w = fmaxf(vprev.w, v.w);
                if (j > 0) {
                    const int pos = (j - 1) * 7 + (i - 1);
                    float4 ov;
                    ov.x = fmaxf(rowmax[i - 1].x, rm.x);
                    ov.y = fmaxf(rowmax[i - 1].y, rm.y);
                    ov.z = fmaxf(rowmax[i - 1].z, rm.z);
                    ov.w = fmaxf(rowmax[i - 1].w, rm.w);
                    // rotated component stores: conflict-free across the warp
#pragma unroll
                    for (int t = 0; t < 4; t++) {
                        const int k = (t + rot) & 3;
                        const float val = (k == 0) ? ov.x : (k == 1) ? ov.y
                                        : (k == 2) ? ov.z : ov.w;
                        s_pool[(chb + k) * 49 + pos] = val;
                    }
                }
                rowmax[i - 1] = rm;
            }
            vprev = v;
        }
    }
    __syncwarp();

    // ---- coalesced flush: warp's 128 channels = 6272 contiguous floats ----
    float* obase = out + ((size_t)roi * CCH + half * 128) * 49;
#pragma unroll 8
    for (int idx = lane; idx < 128 * 49; idx += 32)
        obase[idx] = s_pool[idx];
}

extern "C" void kernel_launch(void* const* d_in, const int* in_sizes, int n_in,
                              void* d_out, int out_size)
{
    const float* feat = (const float*)d_in[0];  // [4,256,64,64] f32
    const float* rois = (const float*)d_in[1];  // [N,5] f32
    float* out = (float*)d_out;                 // [N,256,7,7] f32
    const int N = in_sizes[1] / 5;

    dim3 tb(32, 8);
    dim3 tg(NPIX / 32, CCH / 32, 4);
    transpose_kernel<<<tg, tb>>>(feat);

    roialign_maxpool_kernel<<<N * 2, 32>>>(rois, out);
}

// round 5
// speedup vs baseline: 2.4780x; 2.4780x over previous
#include <cuda_runtime.h>

#define CCH 256
#define HH 64
#define WW 64
#define NPIX (HH * WW)

// 4 * 4096 * 256 floats = 16 MB channels-last scratch
__device__ float g_feat_nhwc[4 * NPIX * CCH];

// NCHW -> NHWC transpose: per batch, [C=256][P=4096] -> [P][C]
__global__ __launch_bounds__(256) void transpose_kernel(const float* __restrict__ feat)
{
    __shared__ float tile[32][33];
    const int b  = blockIdx.z;
    const int p0 = blockIdx.x * 32;
    const int c0 = blockIdx.y * 32;
    const int tx = threadIdx.x;
    const int ty = threadIdx.y;
    const float* src = feat + (size_t)b * CCH * NPIX;
    float* dst = g_feat_nhwc + (size_t)b * NPIX * CCH;
#pragma unroll
    for (int i = 0; i < 32; i += 8)
        tile[ty + i][tx] = src[(size_t)(c0 + ty + i) * NPIX + (p0 + tx)];
    __syncthreads();
#pragma unroll
    for (int i = 0; i < 32; i += 8)
        dst[(size_t)(p0 + ty + i) * CCH + (c0 + tx)] = tile[tx][ty + i];
}

// Block = 128 threads (4 warps). Each block: one ROI, 128 channels
// (warp = 32 consecutive channels, lane = channel -> every gather is one
// fully-coalesced 128B wavefront). Geometry packed as int4+float4 so each
// bin costs 2 LDS.128 broadcasts instead of 8 scalar LDS.
__global__ __launch_bounds__(128) void roialign_maxpool_kernel(
    const float* __restrict__ rois,
    float* __restrict__ out)
{
    __shared__ int4   s_off[64];
    __shared__ float4 s_w[64];
    __shared__ int    s_b;
    __shared__ float  s_pool[4][32 * 49];   // [warp][ch][49] == output order

    const int roi  = blockIdx.x >> 1;
    const int half = blockIdx.x & 1;
    const int tid  = threadIdx.x;

    // ---- per-ROI geometry, one bin per thread 0..63 (valid folded into w) ----
    if (tid < 64) {
        const float* r = rois + (size_t)roi * 5;
        const float x1 = r[1] * 0.0625f;
        const float y1 = r[2] * 0.0625f;
        const float x2 = r[3] * 0.0625f;
        const float y2 = r[4] * 0.0625f;
        const float bh = (y2 - y1) / 7.0f;
        const float bw = (x2 - x1) / 7.0f;
        const int j = tid >> 3;
        const int i = tid & 7;
        const float ys = y1 + bh * (float)j;
        const float xs = x1 + bw * (float)i;
        const bool valid = (ys >= 0.0f) && (ys < (float)HH) &&
                           (xs >= 0.0f) && (xs < (float)WW);
        const float y0 = floorf(ys);
        const float x0 = floorf(xs);
        const float ly = ys - y0;
        const float lx = xs - x0;
        int iy0 = min(max((int)y0, 0), HH - 1);
        int ix0 = min(max((int)x0, 0), WW - 1);
        int iy1 = min(iy0 + 1, HH - 1);
        int ix1 = min(ix0 + 1, WW - 1);
        float hy = 1.0f - ly, hx = 1.0f - lx;
        float w00 = hy * hx, w01 = hy * lx, w10 = ly * hx, w11 = ly * lx;
        if (!valid) { w00 = 0.0f; w01 = 0.0f; w10 = 0.0f; w11 = 0.0f; }
        // offsets in floats within the batch plane (NHWC: pixel * 256)
        s_off[tid] = make_int4((iy0 * WW + ix0) * CCH, (iy0 * WW + ix1) * CCH,
                               (iy1 * WW + ix0) * CCH, (iy1 * WW + ix1) * CCH);
        s_w[tid] = make_float4(w00, w01, w10, w11);
        if (tid == 0) s_b = (int)r[0];
    }
    __syncthreads();

    const int warp = tid >> 5;
    const int lane = tid & 31;
    const int c    = half * 128 + warp * 32 + lane;   // this thread's channel
    const float* p = g_feat_nhwc + (size_t)s_b * (NPIX * CCH) + c;
    float* pool = &s_pool[warp][0];

    float prev[8], cur[8];
#pragma unroll
    for (int j = 0; j < 8; j++) {
#pragma unroll
        for (int i = 0; i < 8; i++) {
            const int bin = j * 8 + i;
            const int4   o = s_off[bin];   // one LDS.128 broadcast
            const float4 w = s_w[bin];     // one LDS.128 broadcast
            const float v00 = __ldg(p + o.x);
            const float v01 = __ldg(p + o.y);
            const float v10 = __ldg(p + o.z);
            const float v11 = __ldg(p + o.w);
            cur[i] = w.x * v00 + w.y * v01 + w.z * v10 + w.w * v11;
        }
        if (j > 0) {
#pragma unroll
            for (int pw = 0; pw < 7; pw++) {
                const float m = fmaxf(fmaxf(prev[pw], prev[pw + 1]),
                                      fmaxf(cur[pw],  cur[pw + 1]));
                pool[lane * 49 + (j - 1) * 7 + pw] = m;   // stride 49: conflict-free
            }
        }
#pragma unroll
        for (int i = 0; i < 8; i++) prev[i] = cur[i];
    }
    __syncwarp();

    // ---- coalesced output: warp's 32 channels are 1568 contiguous floats ----
    float* obase = out + ((size_t)roi * CCH + half * 128 + warp * 32) * 49;
#pragma unroll 7
    for (int idx = lane; idx < 32 * 49; idx += 32)
        obase[idx] = pool[idx];
}

extern "C" void kernel_launch(void* const* d_in, const int* in_sizes, int n_in,
                              void* d_out, int out_size)
{
    const float* feat = (const float*)d_in[0];  // [4,256,64,64] f32
    const float* rois = (const float*)d_in[1];  // [N,5] f32
    float* out = (float*)d_out;                 // [N,256,7,7] f32
    const int N = in_sizes[1] / 5;

    dim3 tb(32, 8);
    dim3 tg(NPIX / 32, CCH / 32, 4);
    transpose_kernel<<<tg, tb>>>(feat);

    roialign_maxpool_kernel<<<N * 2, 128>>>(rois, out);
}